// round 6
// baseline (speedup 1.0000x reference)
#include <cuda_runtime.h>
#include <math.h>

#define NGROUPS   4
#define NPERG     10
#define NFILT     40
#define TIME_LEN  64000
#define BATCH     32
#define POOLSZ    401
#define POOLSTR   160
#define OUT_T     400
#define MAX_K     512
#define MAX_WS    512
#define TILE      256          // outputs per block (128 threads x 2)

// Scratch (static device globals — allowed; runtime alloc is not)
__device__ float g_kern[NGROUPS][MAX_K * 20];      // folded: [tpair][(Kc,Ks) x10]
__device__ float g_win [NGROUPS][MAX_WS * NPERG];  // [tap][f]
__device__ float g_mid [4ll * BATCH * TIME_LEN * NPERG];

struct MetaAll {
    int a[4], cs[4], ps[4], k[4], ws[4], Tg[4];
    int gbx[4], Q[4], cum[4];
    long long off[4];
};

// ---- packed f32x2 helpers --------------------------------------------------
__device__ __forceinline__ void fma2(unsigned long long& d,
                                     unsigned long long a,
                                     unsigned long long b) {
    asm("fma.rn.f32x2 %0, %1, %2, %0;" : "+l"(d) : "l"(a), "l"(b));
}
__device__ __forceinline__ unsigned long long pack2(float v) {
    unsigned long long r;
    asm("mov.b64 %0, {%1, %1};" : "=l"(r) : "f"(v));
    return r;
}
__device__ __forceinline__ unsigned long long packpair(float lo, float hi) {
    unsigned long long r;
    asm("mov.b64 %0, {%1, %2};" : "=l"(r) : "f"(lo), "f"(hi));
    return r;
}
__device__ __forceinline__ void unpack2(unsigned long long v, float& lo, float& hi) {
    asm("mov.b64 {%0, %1}, %2;" : "=f"(lo), "=f"(hi) : "l"(v));
}

// ---------------------------------------------------------------------------
// Precompute folded Gabor tables + pooling windows (double precision).
// ---------------------------------------------------------------------------
__global__ void precompute_kernel(const float* __restrict__ cf_in,
                                  const float* __restrict__ bw_in,
                                  const float* __restrict__ pw_in,
                                  MetaAll meta) {
    const int g  = blockIdx.x;
    const int a  = meta.a[g];
    const int k  = meta.k[g];
    const int h  = k >> 1;
    const int ws = meta.ws[g];
    const int cs = meta.cs[g];
    const double PI = 3.14159265358979323846;
    const double Zd = sqrt(2.0 * log(2.0)) / PI;

    for (int idx = threadIdx.x; idx < (h + 1) * 20; idx += blockDim.x) {
        int tp = idx / 20, j = idx % 20;
        int f = j >> 1;
        bool is_sin = j & 1;
        float cff = fminf(fmaxf(cf_in[a + f], 0.f), (float)PI);
        float bwf = fminf(fmaxf(bw_in[a + f], (float)(2.0 * Zd)), (float)(401.0 * Zd));
        double t  = (double)tp;
        double bw = (double)bwf;
        double gauss = exp(-t * t / (2.0 * bw * bw));
        double norm  = 1.0 / (sqrt(2.0 * PI) * bw);
        double ph    = t * (double)cff;
        double v     = norm * gauss * (is_sin ? sin(ph) : cos(ph));
        if (is_sin && tp == 0) v = 0.0;
        g_kern[g][idx] = (float)v;
    }
    for (int idx = threadIdx.x; idx < ws * 10; idx += blockDim.x) {
        int j = idx / 10, f = idx % 10;
        float pwf = fminf(fmaxf(pw_in[a + f], (float)(2.0 / 401.0)), 0.5f);
        double sigma = (double)pwf / (double)cs * 401.0 / (double)ws;
        double hw = 0.5 * (double)(ws - 1);
        double u  = ((double)j - hw) / (sigma * hw);
        g_win[g][idx] = (float)exp(-0.5 * u * u);
    }
}

// ---------------------------------------------------------------------------
// Merged symmetric Gabor conv + modulus^2, one launch for all 4 groups.
// x staged in a cs-split shared layout: sx[(i%cs)*Q + i/cs]. For a fixed tap
// the residue is uniform, so lane l reads sx[bp + l] -> conflict-free.
// ---------------------------------------------------------------------------
__global__ void __launch_bounds__(128, 8) conv_kernel(
        const float* __restrict__ x, MetaAll m) {
    extern __shared__ float sm[];

    const int bid = blockIdx.x;
    const int g = (bid >= m.cum[1]) + (bid >= m.cum[2]) + (bid >= m.cum[3]);
    const int local = bid - m.cum[g];
    const int gbx = m.gbx[g];
    const int bx = local % gbx;
    const int b  = local / gbx;

    const int cs = m.cs[g], k = m.k[g], Tg = m.Tg[g], Q = m.Q[g];
    const int h = k >> 1;
    const int csQ = cs * Q;

    float* skern = sm;                 // (h+1)*20 floats
    float* sx    = sm + (h + 1) * 20;  // cs*Q floats

    const int tid = threadIdx.x;
    const float* kg = g_kern[g];
    for (int i = tid; i < (h + 1) * 20; i += 128) skern[i] = kg[i];

    const int w0 = bx * TILE;
    const int nx = TILE * cs + k;
    const float* xb = x + (long long)b * TIME_LEN;
    const int base = w0 * cs - h;
    for (int i = tid; i < nx; i += 128) {
        int gx = base + i;
        float v = ((unsigned)gx < (unsigned)TIME_LEN) ? xb[gx] : 0.f;
        sx[(i % cs) * Q + (i / cs)] = v;
    }
    __syncthreads();

    unsigned long long acc[2][10];
#pragma unroll
    for (int o = 0; o < 2; ++o)
#pragma unroll
        for (int j = 0; j < 10; ++j) acc[o][j] = 0ull;

    const int l = tid;

    // center tap t=0: coef (Kc0, 0)
    int rp = h % cs;
    int bp = rp * Q + h / cs;
    int rm = rp, bm = bp;
    {
        unsigned long long x0 = pack2(sx[bp + l]);
        unsigned long long x1 = pack2(sx[bp + l + 128]);
        const ulonglong2* cc = (const ulonglong2*)skern;
#pragma unroll
        for (int q = 0; q < 5; ++q) {
            ulonglong2 c = cc[q];
            fma2(acc[0][2*q  ], x0, c.x);
            fma2(acc[0][2*q+1], x0, c.y);
            fma2(acc[1][2*q  ], x1, c.x);
            fma2(acc[1][2*q+1], x1, c.y);
        }
    }

#pragma unroll 2
    for (int t = 1; t <= h; ++t) {
        // uniform incremental split-index update (lands in uniform regs)
        rp++; bp += Q; if (rp == cs) { rp = 0; bp += 1 - csQ; }
        rm--; bm -= Q; if (rm < 0)  { rm = cs - 1; bm += csQ - 1; }

        float xp0 = sx[bp + l],       xm0 = sx[bm + l];
        float xp1 = sx[bp + l + 128], xm1 = sx[bm + l + 128];
        unsigned long long sd0 = packpair(xp0 + xm0, xp0 - xm0);
        unsigned long long sd1 = packpair(xp1 + xm1, xp1 - xm1);

        const ulonglong2* cc = (const ulonglong2*)(skern + t * 20);
#pragma unroll
        for (int q = 0; q < 5; ++q) {
            ulonglong2 c = cc[q];
            fma2(acc[0][2*q  ], sd0, c.x);
            fma2(acc[0][2*q+1], sd0, c.y);
            fma2(acc[1][2*q  ], sd1, c.x);
            fma2(acc[1][2*q+1], sd1, c.y);
        }
    }

    float* mid = g_mid + m.off[g];
#pragma unroll
    for (int o = 0; o < 2; ++o) {
        int w = w0 + o * 128 + tid;
        if (w < Tg) {
            float* op = mid + ((long long)b * Tg + w) * 10;
#pragma unroll
            for (int f = 0; f < 10; ++f) {
                float c, s;
                unpack2(acc[o][f], c, s);
                op[f] = c * c + s * s;
            }
        }
    }
}

// ---------------------------------------------------------------------------
// Merged depthwise Gaussian pooling: grid.y = group, one warp per (b, p).
// ---------------------------------------------------------------------------
__global__ void pool_kernel(float* __restrict__ out, MetaAll m) {
    const int g = blockIdx.y;
    const int ws = m.ws[g], ps = m.ps[g], Tg = m.Tg[g], a = m.a[g];
    const long long off = m.off[g];

    extern __shared__ float swin[];
    const float* wg = g_win[g];
    for (int i = threadIdx.x; i < ws * 10; i += blockDim.x) swin[i] = wg[i];
    __syncthreads();

    int warp = blockIdx.x * (blockDim.x >> 5) + (threadIdx.x >> 5);
    int lane = threadIdx.x & 31;
    if (warp >= BATCH * OUT_T) return;
    int p = warp % OUT_T;
    int b = warp / OUT_T;

    const float* mrow = g_mid + off + (long long)b * Tg * 10;
    int t0 = p * ps - ws / 2;

    float2 acc2[5];
#pragma unroll
    for (int q = 0; q < 5; ++q) acc2[q] = make_float2(0.f, 0.f);

    for (int j = lane; j < ws; j += 32) {
        int t = t0 + j;
        if ((unsigned)t < (unsigned)Tg) {
            const float2* row = (const float2*)(mrow + (long long)t * 10);
            const float2* wr  = (const float2*)(swin + j * 10);
#pragma unroll
            for (int q = 0; q < 5; ++q) {
                float2 rv = row[q], wv = wr[q];
                acc2[q].x = fmaf(wv.x, rv.x, acc2[q].x);
                acc2[q].y = fmaf(wv.y, rv.y, acc2[q].y);
            }
        }
    }

#pragma unroll
    for (int o = 16; o; o >>= 1)
#pragma unroll
        for (int q = 0; q < 5; ++q) {
            acc2[q].x += __shfl_down_sync(0xffffffffu, acc2[q].x, o);
            acc2[q].y += __shfl_down_sync(0xffffffffu, acc2[q].y, o);
        }

    if (lane == 0) {
        float* op = out + ((long long)b * OUT_T + p) * 40 + a;
#pragma unroll
        for (int q = 0; q < 5; ++q) {
            op[2*q]     = acc2[q].x;
            op[2*q + 1] = acc2[q].y;
        }
    }
}

// ---------------------------------------------------------------------------
// Host: replicate _mel_gabor_init + _group_meta exactly.
// ---------------------------------------------------------------------------
static void build_meta(MetaAll& m) {
    const double PI = 3.14159265358979323846;
    double freqs[257];
    for (int i = 0; i < 257; ++i) freqs[i] = 8000.0 * (double)i / 256.0;
    auto hz2mel = [](double f) { return 2595.0 * log10(1.0 + f / 700.0); };
    auto mel2hz = [](double mm) { return 700.0 * (pow(10.0, mm / 2595.0) - 1.0); };
    double mlo = hz2mel(60.0), mhi = hz2mel(7800.0);
    double hz[42];
    for (int i = 0; i < 42; ++i) hz[i] = mel2hz(mlo + (mhi - mlo) * (double)i / 41.0);

    const double Zd = sqrt(2.0 * log(2.0)) / PI;
    float cff[NFILT], bwf[NFILT];
    for (int i = 0; i < NFILT; ++i) {
        double l = hz[i], c = hz[i + 1], r = hz[i + 2];
        double peak = -1.0; int cb = 0;
        double vals[257];
        for (int j = 0; j < 257; ++j) {
            double v = (freqs[j] - l) / (c - l);
            double v2 = (r - freqs[j]) / (r - c);
            if (v2 < v) v = v2;
            if (v < 0.0) v = 0.0;
            vals[j] = sqrt(v);
            if (vals[j] > peak) { peak = vals[j]; cb = j; }
        }
        int fwhm = 0;
        for (int j = 0; j < 257; ++j) if (vals[j] >= 0.5 * peak) fwhm++;
        float cfv = (float)((double)cb * 2.0 * PI / 512.0);
        float bwv = (float)(sqrt(2.0 * log(2.0)) * 512.0 / (PI * (double)fwhm));
        cfv = fminf(fmaxf(cfv, 0.f), (float)PI);
        bwv = fminf(fmaxf(bwv, (float)(2.0 * Zd)), (float)(401.0 * Zd));
        cff[i] = cfv; bwf[i] = bwv;
    }

    const int divs[12] = {1, 2, 4, 5, 8, 10, 16, 20, 32, 40, 80, 160};
    long long off = 0;
    int cum = 0;
    for (int g = 0; g < NGROUPS; ++g) {
        int a = g * NPERG, b = a + NPERG;
        float cmax = -1.f, bmax = -1.f;
        for (int i = a; i < b; ++i) {
            if (cff[i] > cmax) cmax = cff[i];
            if (bwf[i] > bmax) bmax = bwf[i];
        }
        double s = PI / (double)cmax;          // STRIDE_FACTOR = 1
        if (s < 1.0) s = 1.0;
        int cs = 1;
        for (int d = 0; d < 12; ++d) if ((double)divs[d] <= s) cs = divs[d];
        int k = (int)((double)bmax * 3.0);
        k += 1 - (k % 2);
        int ws = (int)(401.0 / (double)cs + 0.5);
        ws += 1 - (ws % 2);
        if (k > MAX_K - 1) k = MAX_K - 1;      // never hit: bw clip caps k at 451
        if (ws > MAX_WS - 1) ws = MAX_WS - 1;
        m.a[g] = a; m.cs[g] = cs; m.ps[g] = POOLSTR / cs;
        m.k[g] = k; m.ws[g] = ws; m.Tg[g] = TIME_LEN / cs;
        m.gbx[g] = (m.Tg[g] + TILE - 1) / TILE;
        m.Q[g] = TILE + (k + cs - 1) / cs + 1;
        m.cum[g] = cum;
        cum += m.gbx[g] * BATCH;
        m.off[g] = off;
        off += (long long)BATCH * (TIME_LEN / cs) * NPERG;
    }
}

extern "C" void kernel_launch(void* const* d_in, const int* in_sizes, int n_in,
                              void* d_out, int out_size) {
    const float* x  = (const float*)d_in[0];
    const float* cf = (const float*)d_in[1];
    const float* bw = (const float*)d_in[2];
    const float* pw = (const float*)d_in[3];
    float* out = (float*)d_out;

    MetaAll m;
    build_meta(m);

    // conv smem = max over groups of kernel table + split x tile
    size_t conv_smem = 0;
    int total_blocks = 0;
    for (int g = 0; g < NGROUPS; ++g) {
        int h = m.k[g] >> 1;
        size_t s = (size_t)((h + 1) * 20 + m.cs[g] * m.Q[g]) * sizeof(float);
        if (s > conv_smem) conv_smem = s;
        total_blocks += m.gbx[g] * BATCH;
    }
    cudaFuncSetAttribute(conv_kernel, cudaFuncAttributeMaxDynamicSharedMemorySize,
                         (int)conv_smem);

    size_t pool_smem = 0;
    for (int g = 0; g < NGROUPS; ++g) {
        size_t s = (size_t)(m.ws[g] * NPERG) * sizeof(float);
        if (s > pool_smem) pool_smem = s;
    }

    precompute_kernel<<<NGROUPS, 256>>>(cf, bw, pw, m);

    conv_kernel<<<total_blocks, 128, conv_smem>>>(x, m);

    int pool_bx = (BATCH * OUT_T + 7) / 8;   // 8 warps per 256-thread block
    dim3 pool_grid(pool_bx, NGROUPS);
    pool_kernel<<<pool_grid, 256, pool_smem>>>(out, m);
}

// round 7
// speedup vs baseline: 1.0947x; 1.0947x over previous
#include <cuda_runtime.h>
#include <math.h>

#define NGROUPS   4
#define NPERG     10
#define NFILT     40
#define TIME_LEN  64000
#define BATCH     32
#define POOLSZ    401
#define POOLSTR   160
#define OUT_T     400
#define MAX_K     512
#define MAX_WS    512
#define TILE      512          // outputs per conv block (128 threads x 4)

// Scratch (static device globals — allowed; runtime alloc is not)
__device__ float g_kern[NGROUPS][MAX_K * 20];      // residue-ordered folded table
__device__ float g_win [NGROUPS][MAX_WS * NPERG];  // [tap][f]
__device__ float g_mid [4ll * BATCH * TIME_LEN * NPERG];

struct MetaAll {
    int a[4], cs[4], ps[4], k[4], ws[4], Tg[4], gbx[4], Q[4];
    long long off[4];
};

// ---- packed f32x2 helpers --------------------------------------------------
__device__ __forceinline__ void fma2(unsigned long long& d,
                                     unsigned long long a,
                                     unsigned long long b) {
    asm("fma.rn.f32x2 %0, %1, %2, %0;" : "+l"(d) : "l"(a), "l"(b));
}
__device__ __forceinline__ unsigned long long pack2(float v) {
    unsigned long long r;
    asm("mov.b64 %0, {%1, %1};" : "=l"(r) : "f"(v));
    return r;
}
__device__ __forceinline__ unsigned long long packpair(float lo, float hi) {
    unsigned long long r;
    asm("mov.b64 %0, {%1, %2};" : "=l"(r) : "f"(lo), "f"(hi));
    return r;
}
__device__ __forceinline__ void unpack2(unsigned long long v, float& lo, float& hi) {
    asm("mov.b64 {%0, %1}, %2;" : "=f"(lo), "=f"(hi) : "l"(v));
}

// ---------------------------------------------------------------------------
// Precompute. Gabor table written RESIDUE-ORDERED to match conv_t's stream:
//   slot 0         : t = 0
//   class r'=0     : t = cs, 2cs, ...            (cnt = h/cs)
//   class r'=1..cs-1: t = r', r'+cs, ... <= h    (cnt = (h-r')/cs + 1)
// 20 floats per slot: interleaved (Kc_f, Ks_f), f = 0..9.
// ---------------------------------------------------------------------------
__global__ void precompute_kernel(const float* __restrict__ cf_in,
                                  const float* __restrict__ bw_in,
                                  const float* __restrict__ pw_in,
                                  MetaAll meta) {
    const int g  = blockIdx.x;
    const int a  = meta.a[g];
    const int k  = meta.k[g];
    const int h  = k >> 1;
    const int ws = meta.ws[g];
    const int cs = meta.cs[g];
    const double PI = 3.14159265358979323846;
    const double Zd = sqrt(2.0 * log(2.0)) / PI;

    const int stride = blockDim.x * gridDim.y;
    const int start0 = blockIdx.y * blockDim.x + threadIdx.x;

    for (int idx = start0; idx < (h + 1) * 20; idx += stride) {
        int tp = idx / 20, j = idx % 20;
        int f = j >> 1;
        bool is_sin = j & 1;
        float cff = fminf(fmaxf(cf_in[a + f], 0.f), (float)PI);
        float bwf = fminf(fmaxf(bw_in[a + f], (float)(2.0 * Zd)), (float)(401.0 * Zd));
        double t  = (double)tp;
        double bw = (double)bwf;
        double gauss = exp(-t * t / (2.0 * bw * bw));
        double norm  = 1.0 / (sqrt(2.0 * PI) * bw);
        double ph    = t * (double)cff;
        double v     = norm * gauss * (is_sin ? sin(ph) : cos(ph));
        if (is_sin && tp == 0) v = 0.0;

        int slot;
        if (tp == 0) slot = 0;
        else {
            int r = tp % cs;
            int n = tp / cs;
            if (r == 0) n -= 1;
            int st = 0;
            if (r > 0) {
                st = h / cs;
                for (int rr = 1; rr < r; ++rr) st += (h - rr) / cs + 1;
            }
            slot = 1 + st + n;
        }
        g_kern[g][slot * 20 + j] = (float)v;
    }
    for (int idx = start0; idx < ws * 10; idx += stride) {
        int j = idx / 10, f = idx % 10;
        float pwf = fminf(fmaxf(pw_in[a + f], (float)(2.0 / 401.0)), 0.5f);
        double sigma = (double)pwf / (double)cs * 401.0 / (double)ws;
        double hw = 0.5 * (double)(ws - 1);
        double u  = ((double)j - hw) / (sigma * hw);
        g_win[g][idx] = (float)exp(-0.5 * u * u);
    }
}

// ---------------------------------------------------------------------------
// Templated symmetric Gabor conv + modulus^2, 4 outputs/thread.
// x in CS-split shared layout sx[(i%CS)*Q + i/CS]; taps iterated by residue
// class so plus addrs step +1, minus step -1 — conflict-free, branch-free.
// ---------------------------------------------------------------------------
template<int CS>
__global__ void __launch_bounds__(128, 4) conv_t(
        const float* __restrict__ x, int g, long long off, int k, int Tg, int Q) {
    extern __shared__ float sm[];
    const int h = k >> 1;
    float* skern = sm;                 // (h+1)*20
    float* sx    = sm + (h + 1) * 20;  // CS*Q

    const int tid = threadIdx.x;
    const int b   = blockIdx.y;
    const int w0  = blockIdx.x * TILE;

    const float* kg = g_kern[g];
    for (int i = tid; i < (h + 1) * 20; i += 128) skern[i] = kg[i];

    const int nx = TILE * CS + k;
    const float* xb = x + (long long)b * TIME_LEN;
    const int base = w0 * CS - h;
    for (int i = tid; i < nx; i += 128) {
        int gx = base + i;
        float v = ((unsigned)gx < (unsigned)TIME_LEN) ? xb[gx] : 0.f;
        sx[(i % CS) * Q + i / CS] = v;
    }
    __syncthreads();

    unsigned long long acc[4][10];
#pragma unroll
    for (int o = 0; o < 4; ++o)
#pragma unroll
        for (int j = 0; j < 10; ++j) acc[o][j] = 0ull;

    // center tap t = 0 (coef has Ks = 0 in sin lane)
    {
        const float* sp = sx + (h % CS) * Q + h / CS + tid;
        unsigned long long xv0 = pack2(sp[0]);
        unsigned long long xv1 = pack2(sp[128]);
        unsigned long long xv2 = pack2(sp[256]);
        unsigned long long xv3 = pack2(sp[384]);
        const ulonglong2* cc = (const ulonglong2*)skern;
#pragma unroll
        for (int q = 0; q < 5; ++q) {
            ulonglong2 c = cc[q];
            fma2(acc[0][2*q], xv0, c.x); fma2(acc[0][2*q+1], xv0, c.y);
            fma2(acc[1][2*q], xv1, c.x); fma2(acc[1][2*q+1], xv1, c.y);
            fma2(acc[2][2*q], xv2, c.x); fma2(acc[2][2*q+1], xv2, c.y);
            fma2(acc[3][2*q], xv3, c.x); fma2(acc[3][2*q+1], xv3, c.y);
        }
    }

    const float* cptr = skern + 20;
    for (int rc = 0; rc < CS; ++rc) {
        const int ft  = rc ? rc : CS;                       // first tap of class
        const int cnt = (h >= ft) ? (h - ft) / CS + 1 : 0;
        const float* pp = sx + ((h + ft) % CS) * Q + (h + ft) / CS + tid;
        const float* pm = (h >= ft)
            ? sx + ((h - ft) % CS) * Q + (h - ft) / CS + tid : sx;

#pragma unroll 2
        for (int n = 0; n < cnt; ++n) {
            float xp0 = pp[n      ], xm0 = pm[-n      ];
            float xp1 = pp[n + 128], xm1 = pm[-n + 128];
            float xp2 = pp[n + 256], xm2 = pm[-n + 256];
            float xp3 = pp[n + 384], xm3 = pm[-n + 384];
            unsigned long long sd0 = packpair(xp0 + xm0, xp0 - xm0);
            unsigned long long sd1 = packpair(xp1 + xm1, xp1 - xm1);
            unsigned long long sd2 = packpair(xp2 + xm2, xp2 - xm2);
            unsigned long long sd3 = packpair(xp3 + xm3, xp3 - xm3);
            const ulonglong2* cc = (const ulonglong2*)(cptr + n * 20);
#pragma unroll
            for (int q = 0; q < 5; ++q) {
                ulonglong2 c = cc[q];
                fma2(acc[0][2*q], sd0, c.x); fma2(acc[0][2*q+1], sd0, c.y);
                fma2(acc[1][2*q], sd1, c.x); fma2(acc[1][2*q+1], sd1, c.y);
                fma2(acc[2][2*q], sd2, c.x); fma2(acc[2][2*q+1], sd2, c.y);
                fma2(acc[3][2*q], sd3, c.x); fma2(acc[3][2*q+1], sd3, c.y);
            }
        }
        cptr += cnt * 20;
    }

    float* mid = g_mid + off;
#pragma unroll
    for (int o = 0; o < 4; ++o) {
        int w = w0 + o * 128 + tid;
        if (w < Tg) {
            float* op = mid + ((long long)b * Tg + w) * 10;
#pragma unroll
            for (int f = 0; f < 10; ++f) {
                float c, s;
                unpack2(acc[o][f], c, s);
                op[f] = c * c + s * s;
            }
        }
    }
}

// ---------------------------------------------------------------------------
// Merged depthwise Gaussian pooling: grid.y = group, one warp per (b, p).
// ---------------------------------------------------------------------------
__global__ void pool_kernel(float* __restrict__ out, MetaAll m) {
    const int g = blockIdx.y;
    const int ws = m.ws[g], ps = m.ps[g], Tg = m.Tg[g], a = m.a[g];
    const long long off = m.off[g];

    extern __shared__ float swin[];
    const float* wg = g_win[g];
    for (int i = threadIdx.x; i < ws * 10; i += blockDim.x) swin[i] = wg[i];
    __syncthreads();

    int warp = blockIdx.x * (blockDim.x >> 5) + (threadIdx.x >> 5);
    int lane = threadIdx.x & 31;
    if (warp >= BATCH * OUT_T) return;
    int p = warp % OUT_T;
    int b = warp / OUT_T;

    const float* mrow = g_mid + off + (long long)b * Tg * 10;
    int t0 = p * ps - ws / 2;

    float2 acc2[5];
#pragma unroll
    for (int q = 0; q < 5; ++q) acc2[q] = make_float2(0.f, 0.f);

    for (int j = lane; j < ws; j += 32) {
        int t = t0 + j;
        if ((unsigned)t < (unsigned)Tg) {
            const float2* row = (const float2*)(mrow + (long long)t * 10);
            const float2* wr  = (const float2*)(swin + j * 10);
#pragma unroll
            for (int q = 0; q < 5; ++q) {
                float2 rv = row[q], wv = wr[q];
                acc2[q].x = fmaf(wv.x, rv.x, acc2[q].x);
                acc2[q].y = fmaf(wv.y, rv.y, acc2[q].y);
            }
        }
    }

#pragma unroll
    for (int o = 16; o; o >>= 1)
#pragma unroll
        for (int q = 0; q < 5; ++q) {
            acc2[q].x += __shfl_down_sync(0xffffffffu, acc2[q].x, o);
            acc2[q].y += __shfl_down_sync(0xffffffffu, acc2[q].y, o);
        }

    if (lane == 0) {
        float* op = out + ((long long)b * OUT_T + p) * 40 + a;
#pragma unroll
        for (int q = 0; q < 5; ++q) {
            op[2*q]     = acc2[q].x;
            op[2*q + 1] = acc2[q].y;
        }
    }
}

// ---------------------------------------------------------------------------
// Host: replicate _mel_gabor_init + _group_meta exactly.
// ---------------------------------------------------------------------------
static void build_meta(MetaAll& m) {
    const double PI = 3.14159265358979323846;
    double freqs[257];
    for (int i = 0; i < 257; ++i) freqs[i] = 8000.0 * (double)i / 256.0;
    auto hz2mel = [](double f) { return 2595.0 * log10(1.0 + f / 700.0); };
    auto mel2hz = [](double mm) { return 700.0 * (pow(10.0, mm / 2595.0) - 1.0); };
    double mlo = hz2mel(60.0), mhi = hz2mel(7800.0);
    double hz[42];
    for (int i = 0; i < 42; ++i) hz[i] = mel2hz(mlo + (mhi - mlo) * (double)i / 41.0);

    const double Zd = sqrt(2.0 * log(2.0)) / PI;
    float cff[NFILT], bwf[NFILT];
    for (int i = 0; i < NFILT; ++i) {
        double l = hz[i], c = hz[i + 1], r = hz[i + 2];
        double peak = -1.0; int cb = 0;
        double vals[257];
        for (int j = 0; j < 257; ++j) {
            double v = (freqs[j] - l) / (c - l);
            double v2 = (r - freqs[j]) / (r - c);
            if (v2 < v) v = v2;
            if (v < 0.0) v = 0.0;
            vals[j] = sqrt(v);
            if (vals[j] > peak) { peak = vals[j]; cb = j; }
        }
        int fwhm = 0;
        for (int j = 0; j < 257; ++j) if (vals[j] >= 0.5 * peak) fwhm++;
        float cfv = (float)((double)cb * 2.0 * PI / 512.0);
        float bwv = (float)(sqrt(2.0 * log(2.0)) * 512.0 / (PI * (double)fwhm));
        cfv = fminf(fmaxf(cfv, 0.f), (float)PI);
        bwv = fminf(fmaxf(bwv, (float)(2.0 * Zd)), (float)(401.0 * Zd));
        cff[i] = cfv; bwf[i] = bwv;
    }

    const int divs[12] = {1, 2, 4, 5, 8, 10, 16, 20, 32, 40, 80, 160};
    long long off = 0;
    for (int g = 0; g < NGROUPS; ++g) {
        int a = g * NPERG, b = a + NPERG;
        float cmax = -1.f, bmax = -1.f;
        for (int i = a; i < b; ++i) {
            if (cff[i] > cmax) cmax = cff[i];
            if (bwf[i] > bmax) bmax = bwf[i];
        }
        double s = PI / (double)cmax;          // STRIDE_FACTOR = 1
        if (s < 1.0) s = 1.0;
        int cs = 1;
        for (int d = 0; d < 12; ++d) if ((double)divs[d] <= s) cs = divs[d];
        int k = (int)((double)bmax * 3.0);
        k += 1 - (k % 2);
        int ws = (int)(401.0 / (double)cs + 0.5);
        ws += 1 - (ws % 2);
        if (k > MAX_K - 1) k = MAX_K - 1;      // never hit: bw clip caps k at 451
        if (ws > MAX_WS - 1) ws = MAX_WS - 1;
        m.a[g] = a; m.cs[g] = cs; m.ps[g] = POOLSTR / cs;
        m.k[g] = k; m.ws[g] = ws; m.Tg[g] = TIME_LEN / cs;
        m.gbx[g] = (m.Tg[g] + TILE - 1) / TILE;
        m.Q[g] = TILE + (k + cs - 1) / cs + 1;
        m.off[g] = off;
        off += (long long)BATCH * (TIME_LEN / cs) * NPERG;
    }
}

template<int CS>
static void launch_conv(const float* x, int g, const MetaAll& m) {
    size_t smem = (size_t)(((m.k[g] >> 1) + 1) * 20 + CS * m.Q[g]) * sizeof(float);
    cudaFuncSetAttribute(conv_t<CS>, cudaFuncAttributeMaxDynamicSharedMemorySize,
                         (int)smem);
    dim3 grid(m.gbx[g], BATCH);
    conv_t<CS><<<grid, 128, smem>>>(x, g, m.off[g], m.k[g], m.Tg[g], m.Q[g]);
}

extern "C" void kernel_launch(void* const* d_in, const int* in_sizes, int n_in,
                              void* d_out, int out_size) {
    const float* x  = (const float*)d_in[0];
    const float* cf = (const float*)d_in[1];
    const float* bw = (const float*)d_in[2];
    const float* pw = (const float*)d_in[3];
    float* out = (float*)d_out;

    MetaAll m;
    build_meta(m);

    precompute_kernel<<<dim3(NGROUPS, 8), 256>>>(cf, bw, pw, m);

    for (int g = 0; g < NGROUPS; ++g) {
        switch (m.cs[g]) {
            case 1:  launch_conv<1 >(x, g, m); break;
            case 2:  launch_conv<2 >(x, g, m); break;
            case 4:  launch_conv<4 >(x, g, m); break;
            case 5:  launch_conv<5 >(x, g, m); break;
            case 8:  launch_conv<8 >(x, g, m); break;
            case 10: launch_conv<10>(x, g, m); break;
            case 16: launch_conv<16>(x, g, m); break;
            case 20: launch_conv<20>(x, g, m); break;
            case 32: launch_conv<32>(x, g, m); break;
            default: launch_conv<40>(x, g, m); break;  // divisors of 160 beyond 32
        }
    }

    size_t pool_smem = 0;
    for (int g = 0; g < NGROUPS; ++g) {
        size_t s = (size_t)(m.ws[g] * NPERG) * sizeof(float);
        if (s > pool_smem) pool_smem = s;
    }
    int pool_bx = (BATCH * OUT_T + 7) / 8;   // 8 warps per 256-thread block
    dim3 pool_grid(pool_bx, NGROUPS);
    pool_kernel<<<pool_grid, 256, pool_smem>>>(out, m);
}

// round 8
// speedup vs baseline: 1.3441x; 1.2279x over previous
#include <cuda_runtime.h>
#include <cuda_bf16.h>
#include <math.h>

#define NGROUPS   4
#define NPERG     10
#define NFILT     40
#define TIME_LEN  64000
#define BATCH     32
#define POOLSZ    401
#define POOLSTR   160
#define OUT_T     400
#define MAX_K     512
#define MAX_WS    512
#define TILE      256          // outputs per conv block (128 threads x 2)

// Scratch (static device globals — allowed; runtime alloc is not)
__device__ float g_kern[NGROUPS][MAX_K * 20];          // residue-ordered folded table
__device__ float g_win [NGROUPS][MAX_WS * NPERG];      // [tap][f]
__device__ __nv_bfloat16 g_mid [4ll * BATCH * TIME_LEN * NPERG];

struct MetaAll {
    int a[4], cs[4], ps[4], k[4], ws[4], Tg[4], gbx[4], Q[4];
    long long off[4];
};

// ---- packed f32x2 helpers --------------------------------------------------
__device__ __forceinline__ void fma2(unsigned long long& d,
                                     unsigned long long a,
                                     unsigned long long b) {
    asm("fma.rn.f32x2 %0, %1, %2, %0;" : "+l"(d) : "l"(a), "l"(b));
}
__device__ __forceinline__ unsigned long long pack2(float v) {
    unsigned long long r;
    asm("mov.b64 %0, {%1, %1};" : "=l"(r) : "f"(v));
    return r;
}
__device__ __forceinline__ unsigned long long packpair(float lo, float hi) {
    unsigned long long r;
    asm("mov.b64 %0, {%1, %2};" : "=l"(r) : "f"(lo), "f"(hi));
    return r;
}
__device__ __forceinline__ void unpack2(unsigned long long v, float& lo, float& hi) {
    asm("mov.b64 {%0, %1}, %2;" : "=f"(lo), "=f"(hi) : "l"(v));
}

// ---------------------------------------------------------------------------
// Precompute. Gabor table written RESIDUE-ORDERED to match conv_t's stream:
//   slot 0          : t = 0
//   class r'=0      : t = cs, 2cs, ...            (cnt = h/cs)
//   class r'=1..cs-1: t = r', r'+cs, ... <= h     (cnt = (h-r')/cs + 1)
// 20 floats per slot: interleaved (Kc_f, Ks_f), f = 0..9.
// ---------------------------------------------------------------------------
__global__ void precompute_kernel(const float* __restrict__ cf_in,
                                  const float* __restrict__ bw_in,
                                  const float* __restrict__ pw_in,
                                  MetaAll meta) {
    const int g  = blockIdx.x;
    const int a  = meta.a[g];
    const int k  = meta.k[g];
    const int h  = k >> 1;
    const int ws = meta.ws[g];
    const int cs = meta.cs[g];
    const double PI = 3.14159265358979323846;
    const double Zd = sqrt(2.0 * log(2.0)) / PI;

    const int stride = blockDim.x * gridDim.y;
    const int start0 = blockIdx.y * blockDim.x + threadIdx.x;

    for (int idx = start0; idx < (h + 1) * 20; idx += stride) {
        int tp = idx / 20, j = idx % 20;
        int f = j >> 1;
        bool is_sin = j & 1;
        float cff = fminf(fmaxf(cf_in[a + f], 0.f), (float)PI);
        float bwf = fminf(fmaxf(bw_in[a + f], (float)(2.0 * Zd)), (float)(401.0 * Zd));
        double t  = (double)tp;
        double bw = (double)bwf;
        double gauss = exp(-t * t / (2.0 * bw * bw));
        double norm  = 1.0 / (sqrt(2.0 * PI) * bw);
        double ph    = t * (double)cff;
        double v     = norm * gauss * (is_sin ? sin(ph) : cos(ph));
        if (is_sin && tp == 0) v = 0.0;

        int slot;
        if (tp == 0) slot = 0;
        else {
            int r = tp % cs;
            int n = tp / cs;
            if (r == 0) n -= 1;
            int st = 0;
            if (r > 0) {
                st = h / cs;
                for (int rr = 1; rr < r; ++rr) st += (h - rr) / cs + 1;
            }
            slot = 1 + st + n;
        }
        g_kern[g][slot * 20 + j] = (float)v;
    }
    for (int idx = start0; idx < ws * 10; idx += stride) {
        int j = idx / 10, f = idx % 10;
        float pwf = fminf(fmaxf(pw_in[a + f], (float)(2.0 / 401.0)), 0.5f);
        double sigma = (double)pwf / (double)cs * 401.0 / (double)ws;
        double hw = 0.5 * (double)(ws - 1);
        double u  = ((double)j - hw) / (sigma * hw);
        g_win[g][idx] = (float)exp(-0.5 * u * u);
    }
}

// ---------------------------------------------------------------------------
// Templated symmetric Gabor conv + modulus^2, 2 outputs/thread.
// x in CS-split shared layout sx[(i%CS)*Q + i/CS]; taps iterated by residue
// class so plus addrs step +1, minus step -1 — conflict-free, branch-free.
// Occupancy target 6 blocks/SM (<=80 regs).
// ---------------------------------------------------------------------------
template<int CS>
__global__ void __launch_bounds__(128, 6) conv_t(
        const float* __restrict__ x, int g, long long off, int k, int Tg, int Q) {
    extern __shared__ float sm[];
    const int h = k >> 1;
    float* skern = sm;                 // (h+1)*20
    float* sx    = sm + (h + 1) * 20;  // CS*Q

    const int tid = threadIdx.x;
    const int b   = blockIdx.y;
    const int w0  = blockIdx.x * TILE;

    const float* kg = g_kern[g];
    for (int i = tid; i < (h + 1) * 20; i += 128) skern[i] = kg[i];

    const int nx = TILE * CS + k;
    const float* xb = x + (long long)b * TIME_LEN;
    const int base = w0 * CS - h;
    for (int i = tid; i < nx; i += 128) {
        int gx = base + i;
        float v = ((unsigned)gx < (unsigned)TIME_LEN) ? xb[gx] : 0.f;
        sx[(i % CS) * Q + i / CS] = v;
    }
    __syncthreads();

    unsigned long long acc[2][10];
#pragma unroll
    for (int o = 0; o < 2; ++o)
#pragma unroll
        for (int j = 0; j < 10; ++j) acc[o][j] = 0ull;

    // center tap t = 0 (coef has Ks = 0 in sin lane)
    {
        const float* sp = sx + (h % CS) * Q + h / CS + tid;
        unsigned long long xv0 = pack2(sp[0]);
        unsigned long long xv1 = pack2(sp[128]);
        const ulonglong2* cc = (const ulonglong2*)skern;
#pragma unroll
        for (int q = 0; q < 5; ++q) {
            ulonglong2 c = cc[q];
            fma2(acc[0][2*q], xv0, c.x); fma2(acc[0][2*q+1], xv0, c.y);
            fma2(acc[1][2*q], xv1, c.x); fma2(acc[1][2*q+1], xv1, c.y);
        }
    }

    const float* cptr = skern + 20;
    for (int rc = 0; rc < CS; ++rc) {
        const int ft  = rc ? rc : CS;                       // first tap of class
        const int cnt = (h >= ft) ? (h - ft) / CS + 1 : 0;
        const float* pp = sx + ((h + ft) % CS) * Q + (h + ft) / CS + tid;
        const float* pm = (h >= ft)
            ? sx + ((h - ft) % CS) * Q + (h - ft) / CS + tid : sx;

#pragma unroll 4
        for (int n = 0; n < cnt; ++n) {
            float xp0 = pp[n      ], xm0 = pm[-n      ];
            float xp1 = pp[n + 128], xm1 = pm[-n + 128];
            unsigned long long sd0 = packpair(xp0 + xm0, xp0 - xm0);
            unsigned long long sd1 = packpair(xp1 + xm1, xp1 - xm1);
            const ulonglong2* cc = (const ulonglong2*)(cptr + n * 20);
#pragma unroll
            for (int q = 0; q < 5; ++q) {
                ulonglong2 c = cc[q];
                fma2(acc[0][2*q], sd0, c.x); fma2(acc[0][2*q+1], sd0, c.y);
                fma2(acc[1][2*q], sd1, c.x); fma2(acc[1][2*q+1], sd1, c.y);
            }
        }
        cptr += cnt * 20;
    }

    __nv_bfloat16* mid = g_mid + off;
#pragma unroll
    for (int o = 0; o < 2; ++o) {
        int w = w0 + o * 128 + tid;
        if (w < Tg) {
            __nv_bfloat162* op = (__nv_bfloat162*)(mid + ((long long)b * Tg + w) * 10);
#pragma unroll
            for (int q = 0; q < 5; ++q) {
                float c0, s0, c1, s1;
                unpack2(acc[o][2*q],     c0, s0);
                unpack2(acc[o][2*q + 1], c1, s1);
                op[q] = __floats2bfloat162_rn(c0 * c0 + s0 * s0,
                                              c1 * c1 + s1 * s1);
            }
        }
    }
}

// ---------------------------------------------------------------------------
// Merged depthwise Gaussian pooling: grid.y = group, one warp per (b, p).
// mid is bf16 (halves DRAM traffic); window stays fp32 in shared.
// ---------------------------------------------------------------------------
__global__ void pool_kernel(float* __restrict__ out, MetaAll m) {
    const int g = blockIdx.y;
    const int ws = m.ws[g], ps = m.ps[g], Tg = m.Tg[g], a = m.a[g];
    const long long off = m.off[g];

    extern __shared__ float swin[];
    const float* wg = g_win[g];
    for (int i = threadIdx.x; i < ws * 10; i += blockDim.x) swin[i] = wg[i];
    __syncthreads();

    int warp = blockIdx.x * (blockDim.x >> 5) + (threadIdx.x >> 5);
    int lane = threadIdx.x & 31;
    if (warp >= BATCH * OUT_T) return;
    int p = warp % OUT_T;
    int b = warp / OUT_T;

    const __nv_bfloat16* mrow = g_mid + off + (long long)b * Tg * 10;
    int t0 = p * ps - ws / 2;

    float2 acc2[5];
#pragma unroll
    for (int q = 0; q < 5; ++q) acc2[q] = make_float2(0.f, 0.f);

    for (int j = lane; j < ws; j += 32) {
        int t = t0 + j;
        if ((unsigned)t < (unsigned)Tg) {
            const __nv_bfloat162* row = (const __nv_bfloat162*)(mrow + (long long)t * 10);
            const float2* wr  = (const float2*)(swin + j * 10);
#pragma unroll
            for (int q = 0; q < 5; ++q) {
                float2 rv = __bfloat1622float2(row[q]);
                float2 wv = wr[q];
                acc2[q].x = fmaf(wv.x, rv.x, acc2[q].x);
                acc2[q].y = fmaf(wv.y, rv.y, acc2[q].y);
            }
        }
    }

#pragma unroll
    for (int o = 16; o; o >>= 1)
#pragma unroll
        for (int q = 0; q < 5; ++q) {
            acc2[q].x += __shfl_down_sync(0xffffffffu, acc2[q].x, o);
            acc2[q].y += __shfl_down_sync(0xffffffffu, acc2[q].y, o);
        }

    if (lane == 0) {
        float* op = out + ((long long)b * OUT_T + p) * 40 + a;
#pragma unroll
        for (int q = 0; q < 5; ++q) {
            op[2*q]     = acc2[q].x;
            op[2*q + 1] = acc2[q].y;
        }
    }
}

// ---------------------------------------------------------------------------
// Host: replicate _mel_gabor_init + _group_meta exactly.
// ---------------------------------------------------------------------------
static void build_meta(MetaAll& m) {
    const double PI = 3.14159265358979323846;
    double freqs[257];
    for (int i = 0; i < 257; ++i) freqs[i] = 8000.0 * (double)i / 256.0;
    auto hz2mel = [](double f) { return 2595.0 * log10(1.0 + f / 700.0); };
    auto mel2hz = [](double mm) { return 700.0 * (pow(10.0, mm / 2595.0) - 1.0); };
    double mlo = hz2mel(60.0), mhi = hz2mel(7800.0);
    double hz[42];
    for (int i = 0; i < 42; ++i) hz[i] = mel2hz(mlo + (mhi - mlo) * (double)i / 41.0);

    const double Zd = sqrt(2.0 * log(2.0)) / PI;
    float cff[NFILT], bwf[NFILT];
    for (int i = 0; i < NFILT; ++i) {
        double l = hz[i], c = hz[i + 1], r = hz[i + 2];
        double peak = -1.0; int cb = 0;
        double vals[257];
        for (int j = 0; j < 257; ++j) {
            double v = (freqs[j] - l) / (c - l);
            double v2 = (r - freqs[j]) / (r - c);
            if (v2 < v) v = v2;
            if (v < 0.0) v = 0.0;
            vals[j] = sqrt(v);
            if (vals[j] > peak) { peak = vals[j]; cb = j; }
        }
        int fwhm = 0;
        for (int j = 0; j < 257; ++j) if (vals[j] >= 0.5 * peak) fwhm++;
        float cfv = (float)((double)cb * 2.0 * PI / 512.0);
        float bwv = (float)(sqrt(2.0 * log(2.0)) * 512.0 / (PI * (double)fwhm));
        cfv = fminf(fmaxf(cfv, 0.f), (float)PI);
        bwv = fminf(fmaxf(bwv, (float)(2.0 * Zd)), (float)(401.0 * Zd));
        cff[i] = cfv; bwf[i] = bwv;
    }

    const int divs[12] = {1, 2, 4, 5, 8, 10, 16, 20, 32, 40, 80, 160};
    long long off = 0;
    for (int g = 0; g < NGROUPS; ++g) {
        int a = g * NPERG, b = a + NPERG;
        float cmax = -1.f, bmax = -1.f;
        for (int i = a; i < b; ++i) {
            if (cff[i] > cmax) cmax = cff[i];
            if (bwf[i] > bmax) bmax = bwf[i];
        }
        double s = PI / (double)cmax;          // STRIDE_FACTOR = 1
        if (s < 1.0) s = 1.0;
        int cs = 1;
        for (int d = 0; d < 12; ++d) if ((double)divs[d] <= s) cs = divs[d];
        int k = (int)((double)bmax * 3.0);
        k += 1 - (k % 2);
        int ws = (int)(401.0 / (double)cs + 0.5);
        ws += 1 - (ws % 2);
        if (k > MAX_K - 1) k = MAX_K - 1;      // never hit: bw clip caps k at 451
        if (ws > MAX_WS - 1) ws = MAX_WS - 1;
        m.a[g] = a; m.cs[g] = cs; m.ps[g] = POOLSTR / cs;
        m.k[g] = k; m.ws[g] = ws; m.Tg[g] = TIME_LEN / cs;
        m.gbx[g] = (m.Tg[g] + TILE - 1) / TILE;
        m.Q[g] = TILE + (k + cs - 1) / cs + 1;
        m.off[g] = off;
        off += (long long)BATCH * (TIME_LEN / cs) * NPERG;
    }
}

template<int CS>
static void launch_conv(const float* x, int g, const MetaAll& m) {
    size_t smem = (size_t)(((m.k[g] >> 1) + 1) * 20 + CS * m.Q[g]) * sizeof(float);
    cudaFuncSetAttribute(conv_t<CS>, cudaFuncAttributeMaxDynamicSharedMemorySize,
                         (int)smem);
    dim3 grid(m.gbx[g], BATCH);
    conv_t<CS><<<grid, 128, smem>>>(x, g, m.off[g], m.k[g], m.Tg[g], m.Q[g]);
}

extern "C" void kernel_launch(void* const* d_in, const int* in_sizes, int n_in,
                              void* d_out, int out_size) {
    const float* x  = (const float*)d_in[0];
    const float* cf = (const float*)d_in[1];
    const float* bw = (const float*)d_in[2];
    const float* pw = (const float*)d_in[3];
    float* out = (float*)d_out;

    MetaAll m;
    build_meta(m);

    precompute_kernel<<<dim3(NGROUPS, 8), 256>>>(cf, bw, pw, m);

    for (int g = 0; g < NGROUPS; ++g) {
        switch (m.cs[g]) {
            case 1:  launch_conv<1 >(x, g, m); break;
            case 2:  launch_conv<2 >(x, g, m); break;
            case 4:  launch_conv<4 >(x, g, m); break;
            case 5:  launch_conv<5 >(x, g, m); break;
            case 8:  launch_conv<8 >(x, g, m); break;
            case 10: launch_conv<10>(x, g, m); break;
            case 16: launch_conv<16>(x, g, m); break;
            case 20: launch_conv<20>(x, g, m); break;
            case 32: launch_conv<32>(x, g, m); break;
            default: launch_conv<40>(x, g, m); break;  // divisors of 160 beyond 32
        }
    }

    size_t pool_smem = 0;
    for (int g = 0; g < NGROUPS; ++g) {
        size_t s = (size_t)(m.ws[g] * NPERG) * sizeof(float);
        if (s > pool_smem) pool_smem = s;
    }
    int pool_bx = (BATCH * OUT_T + 7) / 8;   // 8 warps per 256-thread block
    dim3 pool_grid(pool_bx, NGROUPS);
    pool_kernel<<<pool_grid, 256, pool_smem>>>(out, m);
}

// round 9
// speedup vs baseline: 2.2210x; 1.6524x over previous
#include <cuda_runtime.h>
#include <cuda_fp16.h>
#include <math.h>

#define NGROUPS   4
#define NPERG     10
#define NFILT     40
#define TIME_LEN  64000
#define BATCH     32
#define POOLSZ    401
#define POOLSTR   160
#define OUT_T     400
#define MAX_WS    512
#define MAX_KH    480            // kstr max (kpad<=464 + 8)

// Scratch (static device globals — allowed; runtime alloc is not)
__device__ __half g_kernh[NGROUPS][24 * MAX_KH];   // B matrix: [channel][tap], fp16, zero-padded
__device__ float  g_win  [NGROUPS][MAX_WS * NPERG];
__device__ __half g_mid  [4ll * BATCH * TIME_LEN * NPERG];

struct MetaAll {
    int a[4], cs[4], ps[4], k[4], ws[4], Tg[4], kpad[4], kstr[4];
    long long off[4];
};

// ---------------------------------------------------------------------------
// Precompute: B table fp16 [n][tap] (n = 2f + (0:cos,1:sin), padded to 24 ch,
// kstr taps) + fp32 pooling windows. Double precision trig.
// ---------------------------------------------------------------------------
__global__ void precompute_kernel(const float* __restrict__ cf_in,
                                  const float* __restrict__ bw_in,
                                  const float* __restrict__ pw_in,
                                  MetaAll meta) {
    const int g  = blockIdx.x;
    const int a  = meta.a[g];
    const int k  = meta.k[g];
    const int h  = k >> 1;
    const int ws = meta.ws[g];
    const int cs = meta.cs[g];
    const int kstr = meta.kstr[g];
    const double PI = 3.14159265358979323846;
    const double Zd = sqrt(2.0 * log(2.0)) / PI;

    const int stride = blockDim.x * gridDim.y;
    const int start0 = blockIdx.y * blockDim.x + threadIdx.x;

    for (int idx = start0; idx < 24 * kstr; idx += stride) {
        int n = idx / kstr, tt = idx % kstr;
        double v = 0.0;
        if (n < 20 && tt < k) {
            int f = n >> 1;
            bool is_sin = n & 1;
            float cff = fminf(fmaxf(cf_in[a + f], 0.f), (float)PI);
            float bwf = fminf(fmaxf(bw_in[a + f], (float)(2.0 * Zd)), (float)(401.0 * Zd));
            double t  = (double)(tt - h);
            double bw = (double)bwf;
            double gauss = exp(-t * t / (2.0 * bw * bw));
            double norm  = 1.0 / (sqrt(2.0 * PI) * bw);
            double ph    = t * (double)cff;
            v = norm * gauss * (is_sin ? sin(ph) : cos(ph));
        }
        g_kernh[g][n * kstr + tt] = __float2half_rn((float)v);
    }
    for (int idx = start0; idx < ws * 10; idx += stride) {
        int j = idx / 10, f = idx % 10;
        float pwf = fminf(fmaxf(pw_in[a + f], (float)(2.0 / 401.0)), 0.5f);
        double sigma = (double)pwf / (double)cs * 401.0 / (double)ws;
        double hw = 0.5 * (double)(ws - 1);
        double u  = ((double)j - hw) / (sigma * hw);
        g_win[g][idx] = (float)exp(-0.5 * u * u);
    }
}

// ---------------------------------------------------------------------------
// mma.sync m16n8k16 fp16 -> fp32 (HMMA)
// ---------------------------------------------------------------------------
__device__ __forceinline__ void mma16816(float* d,
        unsigned a0, unsigned a1, unsigned a2, unsigned a3,
        unsigned b0, unsigned b1) {
    asm("mma.sync.aligned.m16n8k16.row.col.f32.f16.f16.f32 "
        "{%0,%1,%2,%3}, {%4,%5,%6,%7}, {%8,%9}, {%0,%1,%2,%3};"
        : "+f"(d[0]), "+f"(d[1]), "+f"(d[2]), "+f"(d[3])
        : "r"(a0), "r"(a1), "r"(a2), "r"(a3), "r"(b0), "r"(b1));
}

// ---------------------------------------------------------------------------
// Conv as im2col GEMM. Block = 128 thr = 4 warps, covers 128 output positions.
// Warp w: rows [32w, 32w+32) as two m16 tiles; N = 24 channels (3 n8 tiles).
// A fragments loaded straight from the linear x tile (rows are shifted views);
// odd CS handled by a half-shifted duplicate tile for odd-parity rows.
// Epilogue: lane holds (cos,sin) channel pair -> writes |.|^2 to fp16 mid.
// ---------------------------------------------------------------------------
template<int CS>
__global__ void __launch_bounds__(128) convmma(
        const float* __restrict__ x, int g, long long off,
        int k, int kpad, int kstr, int Tg) {
    extern __shared__ __align__(16) __half smh[];
    __half* Bsh = smh;                       // 24*kstr halves
    const int nx = 128 * CS + kpad;
    __half* xsh  = Bsh + 24 * kstr;          // nx+2 halves
    __half* xsh2 = xsh + nx + 2;             // odd-CS shifted copy

    const int tid = threadIdx.x;
    {   // stage B (zero-padded table) as u32
        const unsigned* s = (const unsigned*)&g_kernh[g][0];
        unsigned* dst = (unsigned*)Bsh;
        const int n32 = 24 * kstr / 2;
        for (int i = tid; i < n32; i += 128) dst[i] = s[i];
    }
    const int w0 = blockIdx.x * 128;
    const int b  = blockIdx.y;
    const int h  = k >> 1;
    const int base = w0 * CS - h;
    const float* xb = x + (long long)b * TIME_LEN;
    for (int i = tid; i < nx; i += 128) {
        int gx = base + i;
        xsh[i] = __float2half_rn(((unsigned)gx < (unsigned)TIME_LEN) ? xb[gx] : 0.f);
        if (CS & 1) {
            int gx2 = gx + 1;
            xsh2[i] = __float2half_rn(((unsigned)gx2 < (unsigned)TIME_LEN) ? xb[gx2] : 0.f);
        }
    }
    __syncthreads();

    const int wid = tid >> 5, l = tid & 31, gq = l >> 2, t4 = l & 3;
    const int cb = 2 * t4;

    // per-row base pointer + half-offset (parity-corrected for odd CS)
    const __half* pr[4]; int orw[4];
#pragma unroll
    for (int j = 0; j < 4; ++j) {
        int r = wid * 32 + gq + j * 8;      // j: 0->tile0 rowA, 1->tile0 rowB, 2/3 -> tile1
        int o = r * CS;
        if ((CS & 1) && (o & 1)) { pr[j] = xsh2; orw[j] = o - 1; }
        else                     { pr[j] = xsh;  orw[j] = o;     }
    }
    const __half* q0 = Bsh + gq * kstr;
    const __half* q1 = Bsh + (8  + gq) * kstr;
    const __half* q2 = Bsh + (16 + gq) * kstr;

    float d[2][3][4];
#pragma unroll
    for (int m2 = 0; m2 < 2; ++m2)
#pragma unroll
        for (int n = 0; n < 3; ++n)
#pragma unroll
            for (int e = 0; e < 4; ++e) d[m2][n][e] = 0.f;

    for (int kk = 0; kk < kpad; kk += 16) {
        const int o = kk + cb;
        unsigned a0 = *(const unsigned*)(pr[0] + orw[0] + o);
        unsigned a1 = *(const unsigned*)(pr[1] + orw[1] + o);
        unsigned a2 = *(const unsigned*)(pr[0] + orw[0] + o + 8);
        unsigned a3 = *(const unsigned*)(pr[1] + orw[1] + o + 8);
        unsigned c0 = *(const unsigned*)(pr[2] + orw[2] + o);
        unsigned c1 = *(const unsigned*)(pr[3] + orw[3] + o);
        unsigned c2 = *(const unsigned*)(pr[2] + orw[2] + o + 8);
        unsigned c3 = *(const unsigned*)(pr[3] + orw[3] + o + 8);
        unsigned b00 = *(const unsigned*)(q0 + o), b01 = *(const unsigned*)(q0 + o + 8);
        unsigned b10 = *(const unsigned*)(q1 + o), b11 = *(const unsigned*)(q1 + o + 8);
        unsigned b20 = *(const unsigned*)(q2 + o), b21 = *(const unsigned*)(q2 + o + 8);
        mma16816(d[0][0], a0, a1, a2, a3, b00, b01);
        mma16816(d[0][1], a0, a1, a2, a3, b10, b11);
        mma16816(d[0][2], a0, a1, a2, a3, b20, b21);
        mma16816(d[1][0], c0, c1, c2, c3, b00, b01);
        mma16816(d[1][1], c0, c1, c2, c3, b10, b11);
        mma16816(d[1][2], c0, c1, c2, c3, b20, b21);
    }

    __half* mid = g_mid + off;
    const long long rowbase = (long long)b * Tg + w0;
#pragma unroll
    for (int m2 = 0; m2 < 2; ++m2) {
        int ra = wid * 32 + gq + m2 * 16;
        int rb = ra + 8;
#pragma unroll
        for (int n = 0; n < 3; ++n) {
            int p = n * 4 + t4;              // channel pair index = filter f
            if (p < 10) {
                float v0 = d[m2][n][0] * d[m2][n][0] + d[m2][n][1] * d[m2][n][1];
                float v1 = d[m2][n][2] * d[m2][n][2] + d[m2][n][3] * d[m2][n][3];
                mid[(rowbase + ra) * 10 + p] = __float2half_rn(v0);
                mid[(rowbase + rb) * 10 + p] = __float2half_rn(v1);
            }
        }
    }
}

// ---------------------------------------------------------------------------
// Merged depthwise Gaussian pooling: grid.y = group, one warp per (b, p).
// mid is fp16; window fp32 in shared.
// ---------------------------------------------------------------------------
__global__ void pool_kernel(float* __restrict__ out, MetaAll m) {
    const int g = blockIdx.y;
    const int ws = m.ws[g], ps = m.ps[g], Tg = m.Tg[g], a = m.a[g];
    const long long off = m.off[g];

    extern __shared__ float swin[];
    const float* wg = g_win[g];
    for (int i = threadIdx.x; i < ws * 10; i += blockDim.x) swin[i] = wg[i];
    __syncthreads();

    int warp = blockIdx.x * (blockDim.x >> 5) + (threadIdx.x >> 5);
    int lane = threadIdx.x & 31;
    if (warp >= BATCH * OUT_T) return;
    int p = warp % OUT_T;
    int b = warp / OUT_T;

    const __half* mrow = g_mid + off + (long long)b * Tg * 10;
    int t0 = p * ps - ws / 2;

    float2 acc2[5];
#pragma unroll
    for (int q = 0; q < 5; ++q) acc2[q] = make_float2(0.f, 0.f);

    for (int j = lane; j < ws; j += 32) {
        int t = t0 + j;
        if ((unsigned)t < (unsigned)Tg) {
            const __half2* row = (const __half2*)(mrow + (long long)t * 10);
            const float2* wr = (const float2*)(swin + j * 10);
#pragma unroll
            for (int q = 0; q < 5; ++q) {
                float2 rv = __half22float2(row[q]);
                float2 wv = wr[q];
                acc2[q].x = fmaf(wv.x, rv.x, acc2[q].x);
                acc2[q].y = fmaf(wv.y, rv.y, acc2[q].y);
            }
        }
    }

#pragma unroll
    for (int o = 16; o; o >>= 1)
#pragma unroll
        for (int q = 0; q < 5; ++q) {
            acc2[q].x += __shfl_down_sync(0xffffffffu, acc2[q].x, o);
            acc2[q].y += __shfl_down_sync(0xffffffffu, acc2[q].y, o);
        }

    if (lane == 0) {
        float* op = out + ((long long)b * OUT_T + p) * 40 + a;
#pragma unroll
        for (int q = 0; q < 5; ++q) {
            op[2*q]     = acc2[q].x;
            op[2*q + 1] = acc2[q].y;
        }
    }
}

// ---------------------------------------------------------------------------
// Host: replicate _mel_gabor_init + _group_meta exactly.
// ---------------------------------------------------------------------------
static void build_meta(MetaAll& m) {
    const double PI = 3.14159265358979323846;
    double freqs[257];
    for (int i = 0; i < 257; ++i) freqs[i] = 8000.0 * (double)i / 256.0;
    auto hz2mel = [](double f) { return 2595.0 * log10(1.0 + f / 700.0); };
    auto mel2hz = [](double mm) { return 700.0 * (pow(10.0, mm / 2595.0) - 1.0); };
    double mlo = hz2mel(60.0), mhi = hz2mel(7800.0);
    double hz[42];
    for (int i = 0; i < 42; ++i) hz[i] = mel2hz(mlo + (mhi - mlo) * (double)i / 41.0);

    const double Zd = sqrt(2.0 * log(2.0)) / PI;
    float cff[NFILT], bwf[NFILT];
    for (int i = 0; i < NFILT; ++i) {
        double l = hz[i], c = hz[i + 1], r = hz[i + 2];
        double peak = -1.0; int cb = 0;
        double vals[257];
        for (int j = 0; j < 257; ++j) {
            double v = (freqs[j] - l) / (c - l);
            double v2 = (r - freqs[j]) / (r - c);
            if (v2 < v) v = v2;
            if (v < 0.0) v = 0.0;
            vals[j] = sqrt(v);
            if (vals[j] > peak) { peak = vals[j]; cb = j; }
        }
        int fwhm = 0;
        for (int j = 0; j < 257; ++j) if (vals[j] >= 0.5 * peak) fwhm++;
        float cfv = (float)((double)cb * 2.0 * PI / 512.0);
        float bwv = (float)(sqrt(2.0 * log(2.0)) * 512.0 / (PI * (double)fwhm));
        cfv = fminf(fmaxf(cfv, 0.f), (float)PI);
        bwv = fminf(fmaxf(bwv, (float)(2.0 * Zd)), (float)(401.0 * Zd));
        cff[i] = cfv; bwf[i] = bwv;
    }

    const int divs[12] = {1, 2, 4, 5, 8, 10, 16, 20, 32, 40, 80, 160};
    long long off = 0;
    for (int g = 0; g < NGROUPS; ++g) {
        int a = g * NPERG, b = a + NPERG;
        float cmax = -1.f, bmax = -1.f;
        for (int i = a; i < b; ++i) {
            if (cff[i] > cmax) cmax = cff[i];
            if (bwf[i] > bmax) bmax = bwf[i];
        }
        double s = PI / (double)cmax;          // STRIDE_FACTOR = 1
        if (s < 1.0) s = 1.0;
        int cs = 1;
        for (int d = 0; d < 12; ++d) if ((double)divs[d] <= s) cs = divs[d];
        int k = (int)((double)bmax * 3.0);
        k += 1 - (k % 2);
        int ws = (int)(401.0 / (double)cs + 0.5);
        ws += 1 - (ws % 2);
        if (ws > MAX_WS - 1) ws = MAX_WS - 1;
        m.a[g] = a; m.cs[g] = cs; m.ps[g] = POOLSTR / cs;
        m.k[g] = k; m.ws[g] = ws; m.Tg[g] = TIME_LEN / cs;
        m.kpad[g] = ((k + 15) / 16) * 16;
        m.kstr[g] = m.kpad[g] + 8;             // bank-spread row stride
        m.off[g] = off;
        off += (long long)BATCH * (TIME_LEN / cs) * NPERG;
    }
}

template<int CS>
static void launch_conv(const float* x, int g, const MetaAll& m) {
    int nx = 128 * CS + m.kpad[g];
    size_t smem = (size_t)(24 * m.kstr[g] + (nx + 2) * ((CS & 1) ? 2 : 1))
                  * sizeof(__half);
    cudaFuncSetAttribute(convmma<CS>, cudaFuncAttributeMaxDynamicSharedMemorySize,
                         (int)smem);
    dim3 grid(m.Tg[g] / 128, BATCH);           // Tg always divisible by 128
    convmma<CS><<<grid, 128, smem>>>(x, g, m.off[g], m.k[g], m.kpad[g],
                                     m.kstr[g], m.Tg[g]);
}

extern "C" void kernel_launch(void* const* d_in, const int* in_sizes, int n_in,
                              void* d_out, int out_size) {
    const float* x  = (const float*)d_in[0];
    const float* cf = (const float*)d_in[1];
    const float* bw = (const float*)d_in[2];
    const float* pw = (const float*)d_in[3];
    float* out = (float*)d_out;

    MetaAll m;
    build_meta(m);

    precompute_kernel<<<dim3(NGROUPS, 8), 256>>>(cf, bw, pw, m);

    for (int g = 0; g < NGROUPS; ++g) {
        switch (m.cs[g]) {
            case 1:  launch_conv<1 >(x, g, m); break;
            case 2:  launch_conv<2 >(x, g, m); break;
            case 4:  launch_conv<4 >(x, g, m); break;
            case 5:  launch_conv<5 >(x, g, m); break;
            case 8:  launch_conv<8 >(x, g, m); break;
            case 10: launch_conv<10>(x, g, m); break;
            case 16: launch_conv<16>(x, g, m); break;
            case 20: launch_conv<20>(x, g, m); break;
            case 32: launch_conv<32>(x, g, m); break;
            default: launch_conv<40>(x, g, m); break;
        }
    }

    size_t pool_smem = 0;
    for (int g = 0; g < NGROUPS; ++g) {
        size_t s = (size_t)(m.ws[g] * NPERG) * sizeof(float);
        if (s > pool_smem) pool_smem = s;
    }
    int pool_bx = (BATCH * OUT_T + 7) / 8;     // 8 warps per 256-thread block
    dim3 pool_grid(pool_bx, NGROUPS);
    pool_kernel<<<pool_grid, 256, pool_smem>>>(out, m);
}